// round 3
// baseline (speedup 1.0000x reference)
#include <cuda_runtime.h>
#include <cstdint>

#define MAX_NODES 100000
#define D 128          // feature dim == hidden units == out units
#define D4 (D / 4)     // 32 float4 per row

// Scratch: aggregated features (X + neighbor sums). 100000*128*4B = 51.2 MB.
__device__ float g_agg[(size_t)MAX_NODES * D];

// ---------------------------------------------------------------------------
// Kernel 1: agg = X   (vectorized copy; re-initializes scratch every replay)
// ---------------------------------------------------------------------------
__global__ void init_agg_kernel(const float4* __restrict__ X4, float4* __restrict__ agg4, int n4) {
    int i = blockIdx.x * blockDim.x + threadIdx.x;
    if (i < n4) agg4[i] = X4[i];
}

// ---------------------------------------------------------------------------
// Kernel 2: edge scatter. One warp per edge; lane l handles float4 chunk l
// (32 chunks * 4 floats = 128 floats = one full row). Cross-adds both
// directions with vectorized red.global.add.v4.f32 (sm_90+).
// ---------------------------------------------------------------------------
__global__ void edge_scatter_kernel(const float4* __restrict__ X4,
                                    const int* __restrict__ ref_a,
                                    const int* __restrict__ ref_b,
                                    float4* __restrict__ agg4,
                                    int n_edges) {
    int warp = (blockIdx.x * blockDim.x + threadIdx.x) >> 5;
    int lane = threadIdx.x & 31;
    if (warp >= n_edges) return;

    int a = ref_a[warp];
    int b = ref_b[warp];

    float4 xa = X4[(size_t)a * D4 + lane];
    float4 xb = X4[(size_t)b * D4 + lane];

    float4* pa = agg4 + (size_t)a * D4 + lane;
    float4* pb = agg4 + (size_t)b * D4 + lane;

    // agg[a] += X[b] ; agg[b] += X[a]
    asm volatile("red.global.add.v4.f32 [%0], {%1, %2, %3, %4};"
                 :: "l"(pa), "f"(xb.x), "f"(xb.y), "f"(xb.z), "f"(xb.w) : "memory");
    asm volatile("red.global.add.v4.f32 [%0], {%1, %2, %3, %4};"
                 :: "l"(pb), "f"(xa.x), "f"(xa.y), "f"(xa.z), "f"(xa.w) : "memory");
}

// ---------------------------------------------------------------------------
// Kernel 3: fused 2-stage GEMM.
//   H = relu(Agg @ Wh + bh)   [128-row tile staged in SMEM]
//   O = H @ Wo + bo           [written to gmem]
// One CTA = 128 rows x 128 cols. 256 threads, 8x8 strided microtile each.
// SMEM: As (A tile) + Ws (Wh then Wo) + Hs  = 3 * 64 KB = 192 KB dynamic.
// ---------------------------------------------------------------------------
__global__ __launch_bounds__(256, 1)
void fused_gemm_kernel(const float* __restrict__ Wh, const float* __restrict__ bh,
                       const float* __restrict__ Wo, const float* __restrict__ bo,
                       float* __restrict__ out, int n_nodes) {
    extern __shared__ float smem[];
    float* As = smem;               // [128][128]
    float* Ws = smem + 128 * 128;   // [128][128]  (Wh, later Wo)
    float* Hs = smem + 2 * 128 * 128;

    const int tid = threadIdx.x;
    const int tx = tid & 15;        // col group
    const int ty = tid >> 4;        // row group
    const int row0 = blockIdx.x * 128;

    // --- load A tile (guard rows past n_nodes with zeros) ---
    const float4* agg4 = (const float4*)g_agg;
    #pragma unroll
    for (int it = 0; it < 16; ++it) {
        int i = tid + it * 256;            // 0..4095 float4 slots
        int r = i >> 5;                    // row in tile
        int c = i & 31;                    // float4 chunk
        float4 v = make_float4(0.f, 0.f, 0.f, 0.f);
        if (row0 + r < n_nodes) v = agg4[(size_t)(row0 + r) * D4 + c];
        *(float4*)&As[r * 128 + c * 4] = v;
    }
    // --- load Wh ---
    {
        const float4* w4 = (const float4*)Wh;
        #pragma unroll
        for (int it = 0; it < 16; ++it) {
            int i = tid + it * 256;
            *(float4*)&Ws[i * 4] = w4[i];
        }
    }
    __syncthreads();

    // --- GEMM 1: acc = bh; acc += As @ Ws ---
    float acc[8][8];
    #pragma unroll
    for (int j = 0; j < 8; ++j) {
        float bj = bh[tx + 16 * j];
        #pragma unroll
        for (int i = 0; i < 8; ++i) acc[i][j] = bj;
    }
    #pragma unroll 4
    for (int k = 0; k < 128; ++k) {
        float a[8], b[8];
        #pragma unroll
        for (int i = 0; i < 8; ++i) a[i] = As[(ty + 16 * i) * 128 + k];
        #pragma unroll
        for (int j = 0; j < 8; ++j) b[j] = Ws[k * 128 + tx + 16 * j];
        #pragma unroll
        for (int i = 0; i < 8; ++i)
            #pragma unroll
            for (int j = 0; j < 8; ++j) acc[i][j] += a[i] * b[j];
    }

    // --- relu -> Hs ---
    #pragma unroll
    for (int i = 0; i < 8; ++i)
        #pragma unroll
        for (int j = 0; j < 8; ++j)
            Hs[(ty + 16 * i) * 128 + (tx + 16 * j)] = fmaxf(acc[i][j], 0.f);
    __syncthreads();   // everyone done with Ws (Wh) and Hs fully written

    // --- load Wo over Ws ---
    {
        const float4* w4 = (const float4*)Wo;
        #pragma unroll
        for (int it = 0; it < 16; ++it) {
            int i = tid + it * 256;
            *(float4*)&Ws[i * 4] = w4[i];
        }
    }
    __syncthreads();

    // --- GEMM 2: acc = bo; acc += Hs @ Ws ---
    #pragma unroll
    for (int j = 0; j < 8; ++j) {
        float bj = bo[tx + 16 * j];
        #pragma unroll
        for (int i = 0; i < 8; ++i) acc[i][j] = bj;
    }
    #pragma unroll 4
    for (int k = 0; k < 128; ++k) {
        float a[8], b[8];
        #pragma unroll
        for (int i = 0; i < 8; ++i) a[i] = Hs[(ty + 16 * i) * 128 + k];
        #pragma unroll
        for (int j = 0; j < 8; ++j) b[j] = Ws[k * 128 + tx + 16 * j];
        #pragma unroll
        for (int i = 0; i < 8; ++i)
            #pragma unroll
            for (int j = 0; j < 8; ++j) acc[i][j] += a[i] * b[j];
    }

    // --- store O ---
    #pragma unroll
    for (int i = 0; i < 8; ++i) {
        int r = row0 + ty + 16 * i;
        if (r < n_nodes) {
            #pragma unroll
            for (int j = 0; j < 8; ++j)
                out[(size_t)r * 128 + (tx + 16 * j)] = acc[i][j];
        }
    }
}

// ---------------------------------------------------------------------------
extern "C" void kernel_launch(void* const* d_in, const int* in_sizes, int n_in,
                              void* d_out, int out_size) {
    const float* X  = (const float*)d_in[0];
    const int*   ra = (const int*)  d_in[1];
    const int*   rb = (const int*)  d_in[2];
    const float* Wh = (const float*)d_in[3];
    const float* bh = (const float*)d_in[4];
    const float* Wo = (const float*)d_in[5];
    const float* bo = (const float*)d_in[6];
    float* out = (float*)d_out;

    const int n_nodes = in_sizes[0] / D;
    const int n_edges = in_sizes[1];

    float* agg;
    cudaGetSymbolAddress((void**)&agg, g_agg);

    // 1) agg = X
    int n4 = n_nodes * D4;
    init_agg_kernel<<<(n4 + 255) / 256, 256>>>((const float4*)X, (float4*)agg, n4);

    // 2) scatter-add over edges (8 warps per 256-thread CTA)
    int blocks = (n_edges + 7) / 8;
    edge_scatter_kernel<<<blocks, 256>>>((const float4*)X, ra, rb, (float4*)agg, n_edges);

    // 3) fused two-layer GEMM
    const int smem_bytes = 3 * 128 * 128 * sizeof(float);  // 196608
    cudaFuncSetAttribute(fused_gemm_kernel,
                         cudaFuncAttributeMaxDynamicSharedMemorySize, smem_bytes);
    int gblocks = (n_nodes + 127) / 128;
    fused_gemm_kernel<<<gblocks, 256, smem_bytes>>>(Wh, bh, Wo, bo, out, n_nodes);
}

// round 5
// speedup vs baseline: 1.2337x; 1.2337x over previous
#include <cuda_runtime.h>
#include <cuda_bf16.h>
#include <mma.h>
#include <cstdint>

using namespace nvcuda;

#define MAX_NODES 100000
#define D 128
#define D4 (D / 4)

// Scratch: aggregated features. 100000*128*4B = 51.2 MB.
__device__ float g_agg[(size_t)MAX_NODES * D];

// ===========================================================================
// Kernel 1: agg = X
// ===========================================================================
__global__ void init_agg_kernel(const float4* __restrict__ X4, float4* __restrict__ agg4, int n4) {
    int i = blockIdx.x * blockDim.x + threadIdx.x;
    if (i < n4) agg4[i] = X4[i];
}

// ===========================================================================
// Kernel 2: edge scatter (warp/edge, red.global.add.v4.f32)
// ===========================================================================
__global__ void edge_scatter_kernel(const float4* __restrict__ X4,
                                    const int* __restrict__ ref_a,
                                    const int* __restrict__ ref_b,
                                    float4* __restrict__ agg4,
                                    int n_edges) {
    int warp = (blockIdx.x * blockDim.x + threadIdx.x) >> 5;
    int lane = threadIdx.x & 31;
    if (warp >= n_edges) return;
    int a = ref_a[warp];
    int b = ref_b[warp];
    float4 xa = X4[(size_t)a * D4 + lane];
    float4 xb = X4[(size_t)b * D4 + lane];
    float4* pa = agg4 + (size_t)a * D4 + lane;
    float4* pb = agg4 + (size_t)b * D4 + lane;
    asm volatile("red.global.add.v4.f32 [%0], {%1, %2, %3, %4};"
                 :: "l"(pa), "f"(xb.x), "f"(xb.y), "f"(xb.z), "f"(xb.w) : "memory");
    asm volatile("red.global.add.v4.f32 [%0], {%1, %2, %3, %4};"
                 :: "l"(pb), "f"(xa.x), "f"(xa.y), "f"(xa.z), "f"(xa.w) : "memory");
}

// ===========================================================================
// Kernel 3: fused 2-layer GEMM on bf16 tensor cores (wmma, 3-term split).
//   H = relu(Agg @ Wh + bh);  O = H @ Wo + bo
// CTA = 128 rows x 128 cols, 256 threads (8 warps, warp w -> rows 16w..16w+15).
// Each value x = hi + lo (bf16); product = hi*hi + hi*lo + lo*hi (f32 accum).
// ===========================================================================
#define LDA 136   // bf16 leading dim (padded; %8==0)
#define LDH 132   // f32 leading dim (padded; %4==0)

// SMEM layout (bytes)
#define SM_BH  0
#define SM_BO  512
#define SM_AHI 1024
#define SM_ALO (SM_AHI + 128 * LDA * 2)       // +34816
#define SM_WHI (SM_ALO + 128 * LDA * 2)
#define SM_WLO (SM_WHI + 128 * LDA * 2)
#define SM_HF  (SM_WLO + 128 * LDA * 2)
#define SM_TOTAL (SM_HF + 128 * LDH * 4)      // 207872 bytes

__device__ __forceinline__ void split2(float x, __nv_bfloat16& hi, __nv_bfloat16& lo) {
    hi = __float2bfloat16_rn(x);
    lo = __float2bfloat16_rn(x - __bfloat162float(hi));
}

__global__ __launch_bounds__(256, 1)
void fused_wmma_kernel(const float* __restrict__ Wh, const float* __restrict__ bh,
                       const float* __restrict__ Wo, const float* __restrict__ bo,
                       float* __restrict__ out, int n_nodes) {
    extern __shared__ char smem[];
    float*          bh_s = (float*)(smem + SM_BH);
    float*          bo_s = (float*)(smem + SM_BO);
    __nv_bfloat16*  Ahi  = (__nv_bfloat16*)(smem + SM_AHI);
    __nv_bfloat16*  Alo  = (__nv_bfloat16*)(smem + SM_ALO);
    __nv_bfloat16*  Whi  = (__nv_bfloat16*)(smem + SM_WHI);
    __nv_bfloat16*  Wlo  = (__nv_bfloat16*)(smem + SM_WLO);
    float*          Hf   = (float*)(smem + SM_HF);

    const int tid = threadIdx.x;
    const int wid = tid >> 5;
    const int row0 = blockIdx.x * 128;

    if (tid < 128) bh_s[tid] = bh[tid];
    else           bo_s[tid - 128] = bo[tid - 128];

    // --- stage A tile (hi/lo split), rows past n_nodes zeroed ---
    const float4* agg4 = (const float4*)g_agg;
    #pragma unroll
    for (int it = 0; it < 16; ++it) {
        int i = tid + it * 256;            // 4096 float4 slots = 128r x 32q
        int r = i >> 5, c = (i & 31) * 4;
        float4 v = make_float4(0.f, 0.f, 0.f, 0.f);
        if (row0 + r < n_nodes) v = agg4[(size_t)(row0 + r) * D4 + (c >> 2)];
        __nv_bfloat16 h0, l0, h1, l1, h2, l2, h3, l3;
        split2(v.x, h0, l0); split2(v.y, h1, l1);
        split2(v.z, h2, l2); split2(v.w, h3, l3);
        int o = r * LDA + c;
        Ahi[o] = h0; Ahi[o+1] = h1; Ahi[o+2] = h2; Ahi[o+3] = h3;
        Alo[o] = l0; Alo[o+1] = l1; Alo[o+2] = l2; Alo[o+3] = l3;
    }
    // --- stage Wh [k][n] row-major (hi/lo) ---
    {
        const float4* W4 = (const float4*)Wh;
        #pragma unroll
        for (int it = 0; it < 16; ++it) {
            int i = tid + it * 256;
            int k = i >> 5, c = (i & 31) * 4;
            float4 v = W4[i];
            __nv_bfloat16 h0, l0, h1, l1, h2, l2, h3, l3;
            split2(v.x, h0, l0); split2(v.y, h1, l1);
            split2(v.z, h2, l2); split2(v.w, h3, l3);
            int o = k * LDA + c;
            Whi[o] = h0; Whi[o+1] = h1; Whi[o+2] = h2; Whi[o+3] = h3;
            Wlo[o] = l0; Wlo[o+1] = l1; Wlo[o+2] = l2; Wlo[o+3] = l3;
        }
    }
    __syncthreads();

    typedef wmma::fragment<wmma::matrix_a, 16, 16, 16, __nv_bfloat16, wmma::row_major> FragA;
    typedef wmma::fragment<wmma::matrix_b, 16, 16, 16, __nv_bfloat16, wmma::row_major> FragB;
    typedef wmma::fragment<wmma::accumulator, 16, 16, 16, float> FragC;

    // ---------------- GEMM 1 ----------------
    {
        FragC acc[8];
        #pragma unroll
        for (int n = 0; n < 8; ++n) wmma::fill_fragment(acc[n], 0.f);

        for (int k = 0; k < 8; ++k) {
            FragA a_hi, a_lo;
            wmma::load_matrix_sync(a_hi, Ahi + wid * 16 * LDA + k * 16, LDA);
            wmma::load_matrix_sync(a_lo, Alo + wid * 16 * LDA + k * 16, LDA);
            #pragma unroll
            for (int n = 0; n < 8; ++n) {
                FragB b_hi, b_lo;
                wmma::load_matrix_sync(b_hi, Whi + k * 16 * LDA + n * 16, LDA);
                wmma::mma_sync(acc[n], a_hi, b_hi, acc[n]);
                wmma::mma_sync(acc[n], a_lo, b_hi, acc[n]);
                wmma::load_matrix_sync(b_lo, Wlo + k * 16 * LDA + n * 16, LDA);
                wmma::mma_sync(acc[n], a_hi, b_lo, acc[n]);
            }
        }
        #pragma unroll
        for (int n = 0; n < 8; ++n)
            wmma::store_matrix_sync(Hf + wid * 16 * LDH + n * 16, acc[n], LDH, wmma::mem_row_major);
    }
    __syncthreads();   // H done; W buffers free

    // --- bias + relu + re-split H into A buffers; then stage Wo over W ---
    #pragma unroll
    for (int it = 0; it < 16; ++it) {
        int i = tid + it * 256;
        int r = i >> 5, c = (i & 31) * 4;
        float4 v = *(const float4*)&Hf[r * LDH + c];
        float x0 = fmaxf(v.x + bh_s[c + 0], 0.f);
        float x1 = fmaxf(v.y + bh_s[c + 1], 0.f);
        float x2 = fmaxf(v.z + bh_s[c + 2], 0.f);
        float x3 = fmaxf(v.w + bh_s[c + 3], 0.f);
        __nv_bfloat16 h0, l0, h1, l1, h2, l2, h3, l3;
        split2(x0, h0, l0); split2(x1, h1, l1);
        split2(x2, h2, l2); split2(x3, h3, l3);
        int o = r * LDA + c;
        Ahi[o] = h0; Ahi[o+1] = h1; Ahi[o+2] = h2; Ahi[o+3] = h3;
        Alo[o] = l0; Alo[o+1] = l1; Alo[o+2] = l2; Alo[o+3] = l3;
    }
    {
        const float4* W4 = (const float4*)Wo;
        #pragma unroll
        for (int it = 0; it < 16; ++it) {
            int i = tid + it * 256;
            int k = i >> 5, c = (i & 31) * 4;
            float4 v = W4[i];
            __nv_bfloat16 h0, l0, h1, l1, h2, l2, h3, l3;
            split2(v.x, h0, l0); split2(v.y, h1, l1);
            split2(v.z, h2, l2); split2(v.w, h3, l3);
            int o = k * LDA + c;
            Whi[o] = h0; Whi[o+1] = h1; Whi[o+2] = h2; Whi[o+3] = h3;
            Wlo[o] = l0; Wlo[o+1] = l1; Wlo[o+2] = l2; Wlo[o+3] = l3;
        }
    }
    __syncthreads();

    // ---------------- GEMM 2 ----------------
    {
        FragC acc[8];
        #pragma unroll
        for (int n = 0; n < 8; ++n) wmma::fill_fragment(acc[n], 0.f);

        for (int k = 0; k < 8; ++k) {
            FragA a_hi, a_lo;
            wmma::load_matrix_sync(a_hi, Ahi + wid * 16 * LDA + k * 16, LDA);
            wmma::load_matrix_sync(a_lo, Alo + wid * 16 * LDA + k * 16, LDA);
            #pragma unroll
            for (int n = 0; n < 8; ++n) {
                FragB b_hi, b_lo;
                wmma::load_matrix_sync(b_hi, Whi + k * 16 * LDA + n * 16, LDA);
                wmma::mma_sync(acc[n], a_hi, b_hi, acc[n]);
                wmma::mma_sync(acc[n], a_lo, b_hi, acc[n]);
                wmma::load_matrix_sync(b_lo, Wlo + k * 16 * LDA + n * 16, LDA);
                wmma::mma_sync(acc[n], a_hi, b_lo, acc[n]);
            }
        }
        #pragma unroll
        for (int n = 0; n < 8; ++n)
            wmma::store_matrix_sync(Hf + wid * 16 * LDH + n * 16, acc[n], LDH, wmma::mem_row_major);
    }
    __syncthreads();

    // --- final: out = Hf + bo (coalesced float4 stores) ---
    #pragma unroll
    for (int it = 0; it < 16; ++it) {
        int i = tid + it * 256;
        int r = i >> 5, c = (i & 31) * 4;
        if (row0 + r < n_nodes) {
            float4 v = *(const float4*)&Hf[r * LDH + c];
            float4 o4;
            o4.x = v.x + bo_s[c + 0];
            o4.y = v.y + bo_s[c + 1];
            o4.z = v.z + bo_s[c + 2];
            o4.w = v.w + bo_s[c + 3];
            *(float4*)&out[(size_t)(row0 + r) * D + c] = o4;
        }
    }
}

// ===========================================================================
extern "C" void kernel_launch(void* const* d_in, const int* in_sizes, int n_in,
                              void* d_out, int out_size) {
    const float* X  = (const float*)d_in[0];
    const int*   ra = (const int*)  d_in[1];
    const int*   rb = (const int*)  d_in[2];
    const float* Wh = (const float*)d_in[3];
    const float* bh = (const float*)d_in[4];
    const float* Wo = (const float*)d_in[5];
    const float* bo = (const float*)d_in[6];
    float* out = (float*)d_out;

    const int n_nodes = in_sizes[0] / D;
    const int n_edges = in_sizes[1];

    float* agg;
    cudaGetSymbolAddress((void**)&agg, g_agg);

    // 1) agg = X
    int n4 = n_nodes * D4;
    init_agg_kernel<<<(n4 + 255) / 256, 256>>>((const float4*)X, (float4*)agg, n4);

    // 2) scatter-add over edges
    int blocks = (n_edges + 7) / 8;
    edge_scatter_kernel<<<blocks, 256>>>((const float4*)X, ra, rb, (float4*)agg, n_edges);

    // 3) fused two-layer tensor-core GEMM (wmma bf16x3)
    cudaFuncSetAttribute(fused_wmma_kernel,
                         cudaFuncAttributeMaxDynamicSharedMemorySize, SM_TOTAL);
    int gblocks = (n_nodes + 127) / 128;
    fused_wmma_kernel<<<gblocks, 256, SM_TOTAL>>>(Wh, bh, Wo, bo, out, n_nodes);
}